// round 14
// baseline (speedup 1.0000x reference)
#include <cuda_runtime.h>
#include <cuda_fp16.h>
#include <cstdint>

// ---------------- problem dims ----------------
#define B_  256
#define S_  8
#define F_  2048
#define H_  8
#define NN  (H_*F_)     // 16384
#define M2  (B_*S_)     // 2048
#define KK  2048        // K per split GEMM
#define ALPHA_ 0.3f

// ---------------- GEMM tiling (R7/R9 proven config) ----------------
#define NKT 32                      // 2048/64
#define A_PITCH 144
#define B_PITCH 272
#define A_ST (128*A_PITCH)          // 18432
#define B_ST (64*B_PITCH)           // 17408
#define STAGE_ST (A_ST + B_ST)      // 35840
#define A_OFF(s) ((s)*STAGE_ST)
#define B_OFF(s) ((s)*STAGE_ST + A_ST)
#define AW_OFF   (3*STAGE_ST)       // 107520
#define SMEM_TOTAL (AW_OFF + 128*4) // 108032 (2 CTAs/SM)

#define CONV_BLKS  1792             // fine-grained conv part2 blocks (tail packing)
#define PREPW_BLKS 2048             // fine-grained W part1 conversion blocks

// ---------------- device scratch ----------------
__device__ __half g_A2[(size_t)M2 * KK];          // 8MB
__device__ __half g_Wf[(size_t)H_ * 2 * F_ * F_]; // 134MB
__device__ __half g_Wh[(size_t)M2 * NN];          // 64MB
__device__ __half g_P0[(size_t)B_ * NN];          // 8MB
__device__ float  g_e [B_ * H_ * S_];             // 16384 floats
__device__ float  g_mbias[F_];

// ---------------- helpers ----------------
__device__ __forceinline__ uint32_t smem_u32(const void* p){
    uint32_t a;
    asm("{ .reg .u64 t; cvta.to.shared.u64 t, %1; cvt.u32.u64 %0, t; }" : "=r"(a) : "l"(p));
    return a;
}
__device__ __forceinline__ void ldsm_x4(uint32_t* r, uint32_t addr){
    asm volatile("ldmatrix.sync.aligned.m8n8.x4.shared.b16 {%0,%1,%2,%3}, [%4];"
                 : "=r"(r[0]),"=r"(r[1]),"=r"(r[2]),"=r"(r[3]) : "r"(addr));
}
__device__ __forceinline__ void ldsm_x4t(uint32_t* r, uint32_t addr){
    asm volatile("ldmatrix.sync.aligned.m8n8.x4.trans.shared.b16 {%0,%1,%2,%3}, [%4];"
                 : "=r"(r[0]),"=r"(r[1]),"=r"(r[2]),"=r"(r[3]) : "r"(addr));
}
__device__ __forceinline__ void mma16816(float* c, const uint32_t* a, const uint32_t* b){
    asm volatile("mma.sync.aligned.m16n8k16.row.col.f32.f16.f16.f32 "
                 "{%0,%1,%2,%3}, {%4,%5,%6,%7}, {%8,%9}, {%0,%1,%2,%3};"
                 : "+f"(c[0]),"+f"(c[1]),"+f"(c[2]),"+f"(c[3])
                 : "r"(a[0]),"r"(a[1]),"r"(a[2]),"r"(a[3]),"r"(b[0]),"r"(b[1]));
}
__device__ __forceinline__ void cp16(uint32_t dst, const void* src){
    asm volatile("cp.async.cg.shared.global [%0], [%1], 16;" :: "r"(dst), "l"(src) : "memory");
}
#define CP_COMMIT() asm volatile("cp.async.commit_group;" ::: "memory")
#define CP_WAIT(n)  asm volatile("cp.async.wait_group %0;" :: "n"(n) : "memory")
__device__ __forceinline__ float lrelu(float z){ return z > 0.f ? z : ALPHA_ * z; }

__device__ __forceinline__ uint2 f4_to_h4(float4 v){
    __half2 lo = __floats2half2_rn(v.x, v.y);
    __half2 hi = __floats2half2_rn(v.z, v.w);
    uint2 pk;
    pk.x = *reinterpret_cast<uint32_t*>(&lo);
    pk.y = *reinterpret_cast<uint32_t*>(&hi);
    return pk;
}

// ---------------------------------------------------------------------------
// Shared GEMM body (R7/R9 proven): 256 thr, warp grid 2Mx4N, warp tile 64x32,
// BK=64, 3 stages, A-frag double-buffered, 2 CTAs/SM.
// FIRST:  P0[b,n](fp16) = inputs[b,0,:](fp16) @ Wf[h,0:F,:]
// !FIRST: Wh = lrelu(A2 @ Wf[h,F:2F,:] + P0);  e += Wh . att_w
// ---------------------------------------------------------------------------
template<bool FIRST>
__device__ __forceinline__ void gemm_body(char* smem, int mBase, int nTile,
                                          const float* __restrict__ att_w)
{
    const uint32_t sb = smem_u32(smem);
    const int tid   = threadIdx.x;
    const int lane  = tid & 31;
    const int wid   = tid >> 5;
    const int warpM = wid & 1;
    const int warpN = wid >> 1;

    const int nBase = nTile * 128;
    const int h     = nTile >> 4;
    const int f0    = (nTile & 15) * 128;

    const size_t aStride = FIRST ? (size_t)(8*KK) : (size_t)KK;
    const __half* gB = g_Wf + ((size_t)h*(2*F_) + (FIRST ? 0 : F_)) * F_ + f0;

    float* sAw = (float*)(smem + AW_OFF);
    if (!FIRST && tid < 128) sAw[tid] = att_w[(size_t)h*F_ + f0 + tid];

    const __half* aSrc = g_A2 + (size_t)(mBase + (tid >> 3))*aStride + (tid & 7)*8;
    const __half* bSrc = gB   + (size_t)(tid >> 4)*F_ + (tid & 15)*8;
    const uint32_t aDst = sb + (uint32_t)(tid >> 3)*A_PITCH + (uint32_t)(tid & 7)*16;
    const uint32_t bDst = sb + A_ST + (uint32_t)(tid >> 4)*B_PITCH + (uint32_t)(tid & 15)*16;

    auto issue = [&](int s, int kt){
        const __half* a = aSrc + (size_t)kt * 64;
        const __half* b = bSrc + (size_t)kt * 64 * F_;
        const uint32_t ad = aDst + (uint32_t)s*STAGE_ST;
        const uint32_t bd = bDst + (uint32_t)s*STAGE_ST;
        #pragma unroll
        for (int i = 0; i < 4; i++)
            cp16(ad + (uint32_t)(i*32*A_PITCH), a + (size_t)(i*32)*aStride);
        #pragma unroll
        for (int i = 0; i < 4; i++)
            cp16(bd + (uint32_t)(i*16*B_PITCH), b + (size_t)(i*16)*F_);
        CP_COMMIT();
    };

    const uint32_t aRow = (uint32_t)(warpM*64 + (lane & 15))*A_PITCH + (((uint32_t)lane >> 4) << 4);
    const uint32_t bRow = (uint32_t)(lane & 15)*B_PITCH
                        + (uint32_t)(warpN*32 + ((lane >> 4) << 3))*2;

    uint32_t af[2][4][4], bfv[2][4];

    auto load_a = [&](int buf, uint32_t aB, int kk16){
        #pragma unroll
        for (int mf = 0; mf < 4; mf++)
            ldsm_x4(af[buf][mf], aB + aRow + (uint32_t)(mf*16)*A_PITCH + (uint32_t)kk16*32);
    };
    auto load_b = [&](uint32_t bB, int kk16){
        #pragma unroll
        for (int nq = 0; nq < 2; nq++)
            ldsm_x4t(bfv[nq], bB + (uint32_t)(kk16*16)*B_PITCH + bRow + (uint32_t)(nq*16)*2);
    };

    float acc[4][4][4];
    #pragma unroll
    for (int a = 0; a < 4; a++)
        #pragma unroll
        for (int b = 0; b < 4; b++)
            #pragma unroll
            for (int c = 0; c < 4; c++) acc[a][b][c] = 0.f;

    issue(0, 0);
    issue(1, 1);
    CP_WAIT(1);
    __syncthreads();
    load_a(0, sb + A_OFF(0), 0);

    for (int kt = 0; kt < NKT; kt++){
        const int s  = kt % 3;
        const int sn = (kt + 1) % 3;
        const uint32_t aB = sb + A_OFF(s);
        const uint32_t bB = sb + B_OFF(s);

        #pragma unroll
        for (int kk = 0; kk < 4; kk++){
            const int cur = kk & 1, nxt = cur ^ 1;
            if (kk == 0 && kt + 2 < NKT)
                issue((kt + 2) % 3, kt + 2);
            load_b(bB, kk);
            if (kk < 3){
                load_a(nxt, aB, kk + 1);
            } else if (kt + 1 < NKT){
                CP_WAIT(1);
                __syncthreads();
                load_a(nxt, sb + A_OFF(sn), 0);
            }
            #pragma unroll
            for (int mf = 0; mf < 4; mf++)
                #pragma unroll
                for (int nq = 0; nq < 2; nq++){
                    mma16816(acc[mf][2*nq],   af[cur][mf], &bfv[nq][0]);
                    mma16816(acc[mf][2*nq+1], af[cur][mf], &bfv[nq][2]);
                }
        }
    }

    const int g  = lane >> 2;
    const int tg = lane & 3;
    #pragma unroll
    for (int mf = 0; mf < 4; mf++){
        const int r0 = mBase + warpM*64 + mf*16 + g;
        const int r1 = r0 + 8;
        if (FIRST){
            #pragma unroll
            for (int nf = 0; nf < 4; nf++){
                const int c0 = nBase + warpN*32 + nf*8 + tg*2;
                *reinterpret_cast<__half2*>(&g_P0[(size_t)r0*NN + c0]) = __floats2half2_rn(acc[mf][nf][0], acc[mf][nf][1]);
                *reinterpret_cast<__half2*>(&g_P0[(size_t)r1*NN + c0]) = __floats2half2_rn(acc[mf][nf][2], acc[mf][nf][3]);
            }
        } else {
            float e0 = 0.f, e1 = 0.f;
            #pragma unroll
            for (int nf = 0; nf < 4; nf++){
                const int lc = warpN*32 + nf*8 + tg*2;
                const int c0 = nBase + lc;
                const float2 p0 = __half22float2(*reinterpret_cast<const __half2*>(&g_P0[(size_t)(r0 >> 3)*NN + c0]));
                const float2 p1 = __half22float2(*reinterpret_cast<const __half2*>(&g_P0[(size_t)(r1 >> 3)*NN + c0]));
                const float v00 = lrelu(acc[mf][nf][0] + p0.x);
                const float v01 = lrelu(acc[mf][nf][1] + p0.y);
                const float v10 = lrelu(acc[mf][nf][2] + p1.x);
                const float v11 = lrelu(acc[mf][nf][3] + p1.y);
                e0 += v00*sAw[lc] + v01*sAw[lc+1];
                e1 += v10*sAw[lc] + v11*sAw[lc+1];
                *reinterpret_cast<__half2*>(&g_Wh[(size_t)r0*NN + c0]) = __floats2half2_rn(v00, v01);
                *reinterpret_cast<__half2*>(&g_Wh[(size_t)r1*NN + c0]) = __floats2half2_rn(v10, v11);
            }
            e0 += __shfl_xor_sync(0xffffffffu, e0, 1);
            e0 += __shfl_xor_sync(0xffffffffu, e0, 2);
            e1 += __shfl_xor_sync(0xffffffffu, e1, 1);
            e1 += __shfl_xor_sync(0xffffffffu, e1, 2);
            if (tg == 0){
                atomicAdd(&g_e[(r0 >> 3)*64 + h*8 + (r0 & 7)], e0);
                atomicAdd(&g_e[(r1 >> 3)*64 + h*8 + (r1 & 7)], e1);
            }
        }
    }
}

// ---------------------------------------------------------------------------
// Merged: blocks [0,256) -> GEMM1 (fp16 B from g_Wf part1);
//         blocks [256,..) -> convert W[:,F:2F,:] fp32 -> g_Wf fp16
// ---------------------------------------------------------------------------
__global__ void __launch_bounds__(256, 2)
gemm1_conv(const float* __restrict__ W)
{
    if (blockIdx.x >= 256){
        const size_t qF = (size_t)F_ * F_ / 4;
        const size_t total = (size_t)H_ * qF;
        const float4* W4 = (const float4*)W;
        uint2* D = (uint2*)g_Wf;
        for (size_t i = (size_t)(blockIdx.x - 256) * 256 + threadIdx.x;
             i < total; i += (size_t)CONV_BLKS * 256){
            const size_t h = i / qF, rem = i - h * qF;
            const size_t idx = h * 2 * qF + qF + rem;   // [F:2F) slice
            D[idx] = f4_to_h4(W4[idx]);
        }
        return;
    }
    extern __shared__ char smem[];
    gemm_body<true>(smem, (blockIdx.x & 1) * 128, blockIdx.x >> 1, nullptr);
}

__global__ void __launch_bounds__(256, 2)
gat_gemm2(const float* __restrict__ att_w)
{
    extern __shared__ char smem[];
    gemm_body<false>(smem, blockIdx.x * 128, blockIdx.y, att_w);
}

// ---------------------------------------------------------------------------
// prep: [0,8) mbias; [8,16) zero ALL g_e (16384); [16,144) inputs->fp16;
//       [144, 144+PREPW_BLKS) W[:,0:F,:] fp32 -> g_Wf fp16
__global__ void __launch_bounds__(256) prep(const float* __restrict__ bias,
                                            const float* __restrict__ in,
                                            const float* __restrict__ W){
    const int tid = threadIdx.x;
    const int bx = blockIdx.x;
    if (bx < 8){
        const int f = bx * 256 + tid;
        float s = 0.f;
        #pragma unroll
        for (int h = 0; h < H_; h++) s += bias[(size_t)h*F_ + f];
        g_mbias[f] = s * 0.125f;
    } else if (bx < 16){
        const int base = (bx - 8) * 2048;          // 8 x 2048 = 16384 = B_*H_*S_
        #pragma unroll
        for (int j = 0; j < 8; j++)
            g_e[base + j*256 + tid] = 0.f;
    } else if (bx < 144){
        const float4* in4 = (const float4*)in;
        uint2* D = (uint2*)g_A2;
        const size_t total = (size_t)M2 * KK / 4;           // 1,048,576 float4
        for (size_t i = (size_t)(bx - 16) * 256 + tid; i < total; i += (size_t)128 * 256)
            D[i] = f4_to_h4(in4[i]);
    } else {
        const size_t qF = (size_t)F_ * F_ / 4;
        const size_t total = (size_t)H_ * qF;
        const float4* W4 = (const float4*)W;
        uint2* D = (uint2*)g_Wf;
        for (size_t i = (size_t)(bx - 144) * 256 + tid;
             i < total; i += (size_t)PREPW_BLKS * 256){
            const size_t h = i / qF, rem = i - h * qF;
            const size_t idx = h * 2 * qF + rem;            // [0:F) slice
            D[idx] = f4_to_h4(W4[idx]);
        }
    }
}

// out[b,s,f] = inputs + mbias + sum_h attn/H * Wh
__global__ void __launch_bounds__(256) gat_out(const float* __restrict__ in,
                                               float* __restrict__ out){
    const int bs = blockIdx.x;
    const int b = bs >> 3, s = bs & 7;
    __shared__ float sAttn[H_];
    const int tid = threadIdx.x;
    if (tid < H_){
        float ev[S_]; float mx = -1e30f;
        #pragma unroll
        for (int s2 = 0; s2 < S_; s2++){ ev[s2] = g_e[b*64 + tid*8 + s2]; mx = fmaxf(mx, ev[s2]); }
        float sum = 0.f;
        #pragma unroll
        for (int s2 = 0; s2 < S_; s2++) sum += __expf(ev[s2] - mx);
        sAttn[tid] = __expf(ev[s] - mx) * 0.125f / sum;
    }
    __syncthreads();
    const float4*  in4 = (const float4*)(in + (size_t)bs * F_);
    const float4*  mb4 = (const float4*)g_mbias;
    const __half2* w2  = (const __half2*)(g_Wh + (size_t)bs * NN);
    float4* o4 = (float4*)(out + (size_t)bs * F_);
    #pragma unroll
    for (int i = tid; i < F_/4; i += 256){
        float4 a = in4[i];
        const float4 mb = mb4[i];
        a.x += mb.x; a.y += mb.y; a.z += mb.z; a.w += mb.w;
        #pragma unroll
        for (int hh = 0; hh < H_; hh++){
            const float aw = sAttn[hh];
            const float2 lo = __half22float2(w2[hh*(F_/2) + 2*i]);
            const float2 hi = __half22float2(w2[hh*(F_/2) + 2*i + 1]);
            a.x += aw*lo.x; a.y += aw*lo.y; a.z += aw*hi.x; a.w += aw*hi.y;
        }
        o4[i] = a;
    }
}

// ---------------------------------------------------------------------------
extern "C" void kernel_launch(void* const* d_in, const int* in_sizes, int n_in,
                              void* d_out, int out_size)
{
    const float* inputs = (const float*)d_in[0];
    const float* W      = (const float*)d_in[1];
    const float* att_w  = (const float*)d_in[2];
    const float* bias   = (const float*)d_in[3];
    float* out = (float*)d_out;

    cudaFuncSetAttribute(gemm1_conv, cudaFuncAttributeMaxDynamicSharedMemorySize, SMEM_TOTAL);
    cudaFuncSetAttribute(gat_gemm2,  cudaFuncAttributeMaxDynamicSharedMemorySize, SMEM_TOTAL);

    prep<<<144 + PREPW_BLKS, 256>>>(bias, inputs, W);
    gemm1_conv<<<256 + CONV_BLKS, 256, SMEM_TOTAL>>>(W);   // GEMM1 || conv part2
    gat_gemm2<<<dim3(16, 128), 256, SMEM_TOTAL>>>(att_w);
    gat_out<<<M2, 256>>>(inputs, out);
}

// round 15
// speedup vs baseline: 1.0737x; 1.0737x over previous
#include <cuda_runtime.h>
#include <cuda_fp16.h>
#include <cstdint>

// ---------------- problem dims ----------------
#define B_  256
#define S_  8
#define F_  2048
#define H_  8
#define NN  (H_*F_)     // 16384
#define M2  (B_*S_)     // 2048
#define KK  2048        // K per split GEMM
#define ALPHA_ 0.3f

// ---------------- GEMM tiling (R7/R9 proven config) ----------------
#define NKT 32                      // 2048/64
#define A_PITCH 144
#define B_PITCH 272
#define A_ST (128*A_PITCH)          // 18432
#define B_ST (64*B_PITCH)           // 17408
#define STAGE_ST (A_ST + B_ST)      // 35840
#define A_OFF(s) ((s)*STAGE_ST)
#define B_OFF(s) ((s)*STAGE_ST + A_ST)
#define AW_OFF   (3*STAGE_ST)       // 107520
#define SMEM_TOTAL (AW_OFF + 128*4) // 108032 (2 CTAs/SM)

#define CONV_BLKS  384              // conv part2 blocks appended to GEMM1 grid (R13 optimum)
#define PREPW_BLKS 896              // W part1 conversion blocks inside prep (R13 optimum)

// ---------------- device scratch ----------------
__device__ __half g_A2[(size_t)M2 * KK];          // 8MB
__device__ __half g_Wf[(size_t)H_ * 2 * F_ * F_]; // 134MB
__device__ __half g_Wh[(size_t)M2 * NN];          // 64MB
__device__ __half g_P0[(size_t)B_ * NN];          // 8MB
__device__ float  g_e [B_ * H_ * S_];             // 16384 floats
__device__ float  g_mbias[F_];

// ---------------- helpers ----------------
__device__ __forceinline__ uint32_t smem_u32(const void* p){
    uint32_t a;
    asm("{ .reg .u64 t; cvta.to.shared.u64 t, %1; cvt.u32.u64 %0, t; }" : "=r"(a) : "l"(p));
    return a;
}
__device__ __forceinline__ void ldsm_x4(uint32_t* r, uint32_t addr){
    asm volatile("ldmatrix.sync.aligned.m8n8.x4.shared.b16 {%0,%1,%2,%3}, [%4];"
                 : "=r"(r[0]),"=r"(r[1]),"=r"(r[2]),"=r"(r[3]) : "r"(addr));
}
__device__ __forceinline__ void ldsm_x4t(uint32_t* r, uint32_t addr){
    asm volatile("ldmatrix.sync.aligned.m8n8.x4.trans.shared.b16 {%0,%1,%2,%3}, [%4];"
                 : "=r"(r[0]),"=r"(r[1]),"=r"(r[2]),"=r"(r[3]) : "r"(addr));
}
__device__ __forceinline__ void mma16816(float* c, const uint32_t* a, const uint32_t* b){
    asm volatile("mma.sync.aligned.m16n8k16.row.col.f32.f16.f16.f32 "
                 "{%0,%1,%2,%3}, {%4,%5,%6,%7}, {%8,%9}, {%0,%1,%2,%3};"
                 : "+f"(c[0]),"+f"(c[1]),"+f"(c[2]),"+f"(c[3])
                 : "r"(a[0]),"r"(a[1]),"r"(a[2]),"r"(a[3]),"r"(b[0]),"r"(b[1]));
}
__device__ __forceinline__ void cp16(uint32_t dst, const void* src){
    asm volatile("cp.async.cg.shared.global [%0], [%1], 16;" :: "r"(dst), "l"(src) : "memory");
}
#define CP_COMMIT() asm volatile("cp.async.commit_group;" ::: "memory")
#define CP_WAIT(n)  asm volatile("cp.async.wait_group %0;" :: "n"(n) : "memory")
__device__ __forceinline__ float lrelu(float z){ return z > 0.f ? z : ALPHA_ * z; }

__device__ __forceinline__ uint2 f4_to_h4(float4 v){
    __half2 lo = __floats2half2_rn(v.x, v.y);
    __half2 hi = __floats2half2_rn(v.z, v.w);
    uint2 pk;
    pk.x = *reinterpret_cast<uint32_t*>(&lo);
    pk.y = *reinterpret_cast<uint32_t*>(&hi);
    return pk;
}

// ---------------------------------------------------------------------------
// Shared GEMM body (R7/R9 proven): 256 thr, warp grid 2Mx4N, warp tile 64x32,
// BK=64, 3 stages, A-frag double-buffered, 2 CTAs/SM.
// FIRST:  P0[b,n](fp16) = inputs[b,0,:](fp16) @ Wf[h,0:F,:]
// !FIRST: Wh = lrelu(A2 @ Wf[h,F:2F,:] + P0);  e += Wh . att_w
// ---------------------------------------------------------------------------
template<bool FIRST>
__device__ __forceinline__ void gemm_body(char* smem, int mBase, int nTile,
                                          const float* __restrict__ att_w)
{
    const uint32_t sb = smem_u32(smem);
    const int tid   = threadIdx.x;
    const int lane  = tid & 31;
    const int wid   = tid >> 5;
    const int warpM = wid & 1;
    const int warpN = wid >> 1;

    const int nBase = nTile * 128;
    const int h     = nTile >> 4;
    const int f0    = (nTile & 15) * 128;

    const size_t aStride = FIRST ? (size_t)(8*KK) : (size_t)KK;
    const __half* gB = g_Wf + ((size_t)h*(2*F_) + (FIRST ? 0 : F_)) * F_ + f0;

    float* sAw = (float*)(smem + AW_OFF);
    if (!FIRST && tid < 128) sAw[tid] = att_w[(size_t)h*F_ + f0 + tid];

    const __half* aSrc = g_A2 + (size_t)(mBase + (tid >> 3))*aStride + (tid & 7)*8;
    const __half* bSrc = gB   + (size_t)(tid >> 4)*F_ + (tid & 15)*8;
    const uint32_t aDst = sb + (uint32_t)(tid >> 3)*A_PITCH + (uint32_t)(tid & 7)*16;
    const uint32_t bDst = sb + A_ST + (uint32_t)(tid >> 4)*B_PITCH + (uint32_t)(tid & 15)*16;

    auto issue = [&](int s, int kt){
        const __half* a = aSrc + (size_t)kt * 64;
        const __half* b = bSrc + (size_t)kt * 64 * F_;
        const uint32_t ad = aDst + (uint32_t)s*STAGE_ST;
        const uint32_t bd = bDst + (uint32_t)s*STAGE_ST;
        #pragma unroll
        for (int i = 0; i < 4; i++)
            cp16(ad + (uint32_t)(i*32*A_PITCH), a + (size_t)(i*32)*aStride);
        #pragma unroll
        for (int i = 0; i < 4; i++)
            cp16(bd + (uint32_t)(i*16*B_PITCH), b + (size_t)(i*16)*F_);
        CP_COMMIT();
    };

    const uint32_t aRow = (uint32_t)(warpM*64 + (lane & 15))*A_PITCH + (((uint32_t)lane >> 4) << 4);
    const uint32_t bRow = (uint32_t)(lane & 15)*B_PITCH
                        + (uint32_t)(warpN*32 + ((lane >> 4) << 3))*2;

    uint32_t af[2][4][4], bfv[2][4];

    auto load_a = [&](int buf, uint32_t aB, int kk16){
        #pragma unroll
        for (int mf = 0; mf < 4; mf++)
            ldsm_x4(af[buf][mf], aB + aRow + (uint32_t)(mf*16)*A_PITCH + (uint32_t)kk16*32);
    };
    auto load_b = [&](uint32_t bB, int kk16){
        #pragma unroll
        for (int nq = 0; nq < 2; nq++)
            ldsm_x4t(bfv[nq], bB + (uint32_t)(kk16*16)*B_PITCH + bRow + (uint32_t)(nq*16)*2);
    };

    float acc[4][4][4];
    #pragma unroll
    for (int a = 0; a < 4; a++)
        #pragma unroll
        for (int b = 0; b < 4; b++)
            #pragma unroll
            for (int c = 0; c < 4; c++) acc[a][b][c] = 0.f;

    issue(0, 0);
    issue(1, 1);
    CP_WAIT(1);
    __syncthreads();
    load_a(0, sb + A_OFF(0), 0);

    for (int kt = 0; kt < NKT; kt++){
        const int s  = kt % 3;
        const int sn = (kt + 1) % 3;
        const uint32_t aB = sb + A_OFF(s);
        const uint32_t bB = sb + B_OFF(s);

        #pragma unroll
        for (int kk = 0; kk < 4; kk++){
            const int cur = kk & 1, nxt = cur ^ 1;
            if (kk == 0 && kt + 2 < NKT)
                issue((kt + 2) % 3, kt + 2);
            load_b(bB, kk);
            if (kk < 3){
                load_a(nxt, aB, kk + 1);
            } else if (kt + 1 < NKT){
                CP_WAIT(1);
                __syncthreads();
                load_a(nxt, sb + A_OFF(sn), 0);
            }
            #pragma unroll
            for (int mf = 0; mf < 4; mf++)
                #pragma unroll
                for (int nq = 0; nq < 2; nq++){
                    mma16816(acc[mf][2*nq],   af[cur][mf], &bfv[nq][0]);
                    mma16816(acc[mf][2*nq+1], af[cur][mf], &bfv[nq][2]);
                }
        }
    }

    const int g  = lane >> 2;
    const int tg = lane & 3;
    #pragma unroll
    for (int mf = 0; mf < 4; mf++){
        const int r0 = mBase + warpM*64 + mf*16 + g;
        const int r1 = r0 + 8;
        if (FIRST){
            #pragma unroll
            for (int nf = 0; nf < 4; nf++){
                const int c0 = nBase + warpN*32 + nf*8 + tg*2;
                *reinterpret_cast<__half2*>(&g_P0[(size_t)r0*NN + c0]) = __floats2half2_rn(acc[mf][nf][0], acc[mf][nf][1]);
                *reinterpret_cast<__half2*>(&g_P0[(size_t)r1*NN + c0]) = __floats2half2_rn(acc[mf][nf][2], acc[mf][nf][3]);
            }
        } else {
            float e0 = 0.f, e1 = 0.f;
            #pragma unroll
            for (int nf = 0; nf < 4; nf++){
                const int lc = warpN*32 + nf*8 + tg*2;
                const int c0 = nBase + lc;
                const float2 p0 = __half22float2(*reinterpret_cast<const __half2*>(&g_P0[(size_t)(r0 >> 3)*NN + c0]));
                const float2 p1 = __half22float2(*reinterpret_cast<const __half2*>(&g_P0[(size_t)(r1 >> 3)*NN + c0]));
                const float v00 = lrelu(acc[mf][nf][0] + p0.x);
                const float v01 = lrelu(acc[mf][nf][1] + p0.y);
                const float v10 = lrelu(acc[mf][nf][2] + p1.x);
                const float v11 = lrelu(acc[mf][nf][3] + p1.y);
                e0 += v00*sAw[lc] + v01*sAw[lc+1];
                e1 += v10*sAw[lc] + v11*sAw[lc+1];
                *reinterpret_cast<__half2*>(&g_Wh[(size_t)r0*NN + c0]) = __floats2half2_rn(v00, v01);
                *reinterpret_cast<__half2*>(&g_Wh[(size_t)r1*NN + c0]) = __floats2half2_rn(v10, v11);
            }
            e0 += __shfl_xor_sync(0xffffffffu, e0, 1);
            e0 += __shfl_xor_sync(0xffffffffu, e0, 2);
            e1 += __shfl_xor_sync(0xffffffffu, e1, 1);
            e1 += __shfl_xor_sync(0xffffffffu, e1, 2);
            if (tg == 0){
                atomicAdd(&g_e[(r0 >> 3)*64 + h*8 + (r0 & 7)], e0);
                atomicAdd(&g_e[(r1 >> 3)*64 + h*8 + (r1 & 7)], e1);
            }
        }
    }
}

// ---------------------------------------------------------------------------
// Merged: blocks [0,256) -> GEMM1 (fp16 B from g_Wf part1);
//         blocks [256,..) -> convert W[:,F:2F,:] fp32 -> g_Wf fp16
// ---------------------------------------------------------------------------
__global__ void __launch_bounds__(256, 2)
gemm1_conv(const float* __restrict__ W)
{
    if (blockIdx.x >= 256){
        const size_t qF = (size_t)F_ * F_ / 4;
        const size_t total = (size_t)H_ * qF;
        const float4* W4 = (const float4*)W;
        uint2* D = (uint2*)g_Wf;
        for (size_t i = (size_t)(blockIdx.x - 256) * 256 + threadIdx.x;
             i < total; i += (size_t)CONV_BLKS * 256){
            const size_t h = i / qF, rem = i - h * qF;
            const size_t idx = h * 2 * qF + qF + rem;   // [F:2F) slice
            D[idx] = f4_to_h4(W4[idx]);
        }
        return;
    }
    extern __shared__ char smem[];
    gemm_body<true>(smem, (blockIdx.x & 1) * 128, blockIdx.x >> 1, nullptr);
}

__global__ void __launch_bounds__(256, 2)
gat_gemm2(const float* __restrict__ att_w)
{
    extern __shared__ char smem[];
    gemm_body<false>(smem, blockIdx.x * 128, blockIdx.y, att_w);
}

// ---------------------------------------------------------------------------
// prep: [0,8) mbias; [8,16) zero ALL g_e (16384); [16,144) inputs->fp16;
//       [144, 144+PREPW_BLKS) W[:,0:F,:] fp32 -> g_Wf fp16
__global__ void __launch_bounds__(256) prep(const float* __restrict__ bias,
                                            const float* __restrict__ in,
                                            const float* __restrict__ W){
    const int tid = threadIdx.x;
    const int bx = blockIdx.x;
    if (bx < 8){
        const int f = bx * 256 + tid;
        float s = 0.f;
        #pragma unroll
        for (int h = 0; h < H_; h++) s += bias[(size_t)h*F_ + f];
        g_mbias[f] = s * 0.125f;
    } else if (bx < 16){
        const int base = (bx - 8) * 2048;          // 8 x 2048 = 16384 = B_*H_*S_
        #pragma unroll
        for (int j = 0; j < 8; j++)
            g_e[base + j*256 + tid] = 0.f;
    } else if (bx < 144){
        const float4* in4 = (const float4*)in;
        uint2* D = (uint2*)g_A2;
        const size_t total = (size_t)M2 * KK / 4;           // 1,048,576 float4
        for (size_t i = (size_t)(bx - 16) * 256 + tid; i < total; i += (size_t)128 * 256)
            D[i] = f4_to_h4(in4[i]);
    } else {
        const size_t qF = (size_t)F_ * F_ / 4;
        const size_t total = (size_t)H_ * qF;
        const float4* W4 = (const float4*)W;
        uint2* D = (uint2*)g_Wf;
        for (size_t i = (size_t)(bx - 144) * 256 + tid;
             i < total; i += (size_t)PREPW_BLKS * 256){
            const size_t h = i / qF, rem = i - h * qF;
            const size_t idx = h * 2 * qF + rem;            // [0:F) slice
            D[idx] = f4_to_h4(W4[idx]);
        }
    }
}

// out[b,s,f] = inputs + mbias + sum_h attn/H * Wh
__global__ void __launch_bounds__(256) gat_out(const float* __restrict__ in,
                                               float* __restrict__ out){
    const int bs = blockIdx.x;
    const int b = bs >> 3, s = bs & 7;
    __shared__ float sAttn[H_];
    const int tid = threadIdx.x;
    if (tid < H_){
        float ev[S_]; float mx = -1e30f;
        #pragma unroll
        for (int s2 = 0; s2 < S_; s2++){ ev[s2] = g_e[b*64 + tid*8 + s2]; mx = fmaxf(mx, ev[s2]); }
        float sum = 0.f;
        #pragma unroll
        for (int s2 = 0; s2 < S_; s2++) sum += __expf(ev[s2] - mx);
        sAttn[tid] = __expf(ev[s] - mx) * 0.125f / sum;
    }
    __syncthreads();
    const float4*  in4 = (const float4*)(in + (size_t)bs * F_);
    const float4*  mb4 = (const float4*)g_mbias;
    const __half2* w2  = (const __half2*)(g_Wh + (size_t)bs * NN);
    float4* o4 = (float4*)(out + (size_t)bs * F_);
    #pragma unroll
    for (int i = tid; i < F_/4; i += 256){
        float4 a = in4[i];
        const float4 mb = mb4[i];
        a.x += mb.x; a.y += mb.y; a.z += mb.z; a.w += mb.w;
        #pragma unroll
        for (int hh = 0; hh < H_; hh++){
            const float aw = sAttn[hh];
            const float2 lo = __half22float2(w2[hh*(F_/2) + 2*i]);
            const float2 hi = __half22float2(w2[hh*(F_/2) + 2*i + 1]);
            a.x += aw*lo.x; a.y += aw*lo.y; a.z += aw*hi.x; a.w += aw*hi.y;
        }
        o4[i] = a;
    }
}

// ---------------------------------------------------------------------------
extern "C" void kernel_launch(void* const* d_in, const int* in_sizes, int n_in,
                              void* d_out, int out_size)
{
    const float* inputs = (const float*)d_in[0];
    const float* W      = (const float*)d_in[1];
    const float* att_w  = (const float*)d_in[2];
    const float* bias   = (const float*)d_in[3];
    float* out = (float*)d_out;

    cudaFuncSetAttribute(gemm1_conv, cudaFuncAttributeMaxDynamicSharedMemorySize, SMEM_TOTAL);
    cudaFuncSetAttribute(gat_gemm2,  cudaFuncAttributeMaxDynamicSharedMemorySize, SMEM_TOTAL);

    prep<<<144 + PREPW_BLKS, 256>>>(bias, inputs, W);
    gemm1_conv<<<256 + CONV_BLKS, 256, SMEM_TOTAL>>>(W);   // GEMM1 || conv part2
    gat_gemm2<<<dim3(16, 128), 256, SMEM_TOTAL>>>(att_w);
    gat_out<<<M2, 256>>>(inputs, out);
}

// round 16
// speedup vs baseline: 1.0773x; 1.0033x over previous
#include <cuda_runtime.h>
#include <cuda_fp16.h>
#include <cstdint>

// ---------------- problem dims ----------------
#define B_  256
#define S_  8
#define F_  2048
#define H_  8
#define NN  (H_*F_)     // 16384
#define M2  (B_*S_)     // 2048
#define KK  2048        // K per split GEMM
#define ALPHA_ 0.3f

// ---------------- GEMM tiling (R7/R9 proven config) ----------------
#define NKT 32                      // 2048/64
#define A_PITCH 144
#define B_PITCH 272
#define A_ST (128*A_PITCH)          // 18432
#define B_ST (64*B_PITCH)           // 17408
#define STAGE_ST (A_ST + B_ST)      // 35840
#define A_OFF(s) ((s)*STAGE_ST)
#define B_OFF(s) ((s)*STAGE_ST + A_ST)
#define AW_OFF   (3*STAGE_ST)       // 107520
#define SMEM_TOTAL (AW_OFF + 128*4) // 108032 (2 CTAs/SM)

#define GEMM1_BLKS 128              // each does BOTH m-tiles of one nTile
#define CONV_BLKS  168              // fills remaining wave-1 slots (296 total)
#define PREPW_BLKS 896              // W part1 conversion blocks inside prep

// ---------------- device scratch ----------------
__device__ __half g_A2[(size_t)M2 * KK];          // 8MB
__device__ __half g_Wf[(size_t)H_ * 2 * F_ * F_]; // 134MB
__device__ __half g_Wh[(size_t)M2 * NN];          // 64MB
__device__ __half g_P0[(size_t)B_ * NN];          // 8MB
__device__ float  g_e [B_ * H_ * S_];             // 16384 floats
__device__ float  g_mbias[F_];

// ---------------- helpers ----------------
__device__ __forceinline__ uint32_t smem_u32(const void* p){
    uint32_t a;
    asm("{ .reg .u64 t; cvta.to.shared.u64 t, %1; cvt.u32.u64 %0, t; }" : "=r"(a) : "l"(p));
    return a;
}
__device__ __forceinline__ void ldsm_x4(uint32_t* r, uint32_t addr){
    asm volatile("ldmatrix.sync.aligned.m8n8.x4.shared.b16 {%0,%1,%2,%3}, [%4];"
                 : "=r"(r[0]),"=r"(r[1]),"=r"(r[2]),"=r"(r[3]) : "r"(addr));
}
__device__ __forceinline__ void ldsm_x4t(uint32_t* r, uint32_t addr){
    asm volatile("ldmatrix.sync.aligned.m8n8.x4.trans.shared.b16 {%0,%1,%2,%3}, [%4];"
                 : "=r"(r[0]),"=r"(r[1]),"=r"(r[2]),"=r"(r[3]) : "r"(addr));
}
__device__ __forceinline__ void mma16816(float* c, const uint32_t* a, const uint32_t* b){
    asm volatile("mma.sync.aligned.m16n8k16.row.col.f32.f16.f16.f32 "
                 "{%0,%1,%2,%3}, {%4,%5,%6,%7}, {%8,%9}, {%0,%1,%2,%3};"
                 : "+f"(c[0]),"+f"(c[1]),"+f"(c[2]),"+f"(c[3])
                 : "r"(a[0]),"r"(a[1]),"r"(a[2]),"r"(a[3]),"r"(b[0]),"r"(b[1]));
}
__device__ __forceinline__ void cp16(uint32_t dst, const void* src){
    asm volatile("cp.async.cg.shared.global [%0], [%1], 16;" :: "r"(dst), "l"(src) : "memory");
}
#define CP_COMMIT() asm volatile("cp.async.commit_group;" ::: "memory")
#define CP_WAIT(n)  asm volatile("cp.async.wait_group %0;" :: "n"(n) : "memory")
__device__ __forceinline__ float lrelu(float z){ return z > 0.f ? z : ALPHA_ * z; }

__device__ __forceinline__ uint2 f4_to_h4(float4 v){
    __half2 lo = __floats2half2_rn(v.x, v.y);
    __half2 hi = __floats2half2_rn(v.z, v.w);
    uint2 pk;
    pk.x = *reinterpret_cast<uint32_t*>(&lo);
    pk.y = *reinterpret_cast<uint32_t*>(&hi);
    return pk;
}

// ---------------------------------------------------------------------------
// Shared GEMM body (R7/R9 proven): 256 thr, warp grid 2Mx4N, warp tile 64x32,
// BK=64, 3 stages, A-frag double-buffered.
// FIRST:  P0[b,n](fp16) = inputs[b,0,:](fp16) @ Wf[h,0:F,:]
// !FIRST: Wh = lrelu(A2 @ Wf[h,F:2F,:] + P0);  e += Wh . att_w
// ---------------------------------------------------------------------------
template<bool FIRST>
__device__ __forceinline__ void gemm_body(char* smem, int mBase, int nTile,
                                          const float* __restrict__ att_w)
{
    const uint32_t sb = smem_u32(smem);
    const int tid   = threadIdx.x;
    const int lane  = tid & 31;
    const int wid   = tid >> 5;
    const int warpM = wid & 1;
    const int warpN = wid >> 1;

    const int nBase = nTile * 128;
    const int h     = nTile >> 4;
    const int f0    = (nTile & 15) * 128;

    const size_t aStride = FIRST ? (size_t)(8*KK) : (size_t)KK;
    const __half* gB = g_Wf + ((size_t)h*(2*F_) + (FIRST ? 0 : F_)) * F_ + f0;

    float* sAw = (float*)(smem + AW_OFF);
    if (!FIRST && tid < 128) sAw[tid] = att_w[(size_t)h*F_ + f0 + tid];

    const __half* aSrc = g_A2 + (size_t)(mBase + (tid >> 3))*aStride + (tid & 7)*8;
    const __half* bSrc = gB   + (size_t)(tid >> 4)*F_ + (tid & 15)*8;
    const uint32_t aDst = sb + (uint32_t)(tid >> 3)*A_PITCH + (uint32_t)(tid & 7)*16;
    const uint32_t bDst = sb + A_ST + (uint32_t)(tid >> 4)*B_PITCH + (uint32_t)(tid & 15)*16;

    auto issue = [&](int s, int kt){
        const __half* a = aSrc + (size_t)kt * 64;
        const __half* b = bSrc + (size_t)kt * 64 * F_;
        const uint32_t ad = aDst + (uint32_t)s*STAGE_ST;
        const uint32_t bd = bDst + (uint32_t)s*STAGE_ST;
        #pragma unroll
        for (int i = 0; i < 4; i++)
            cp16(ad + (uint32_t)(i*32*A_PITCH), a + (size_t)(i*32)*aStride);
        #pragma unroll
        for (int i = 0; i < 4; i++)
            cp16(bd + (uint32_t)(i*16*B_PITCH), b + (size_t)(i*16)*F_);
        CP_COMMIT();
    };

    const uint32_t aRow = (uint32_t)(warpM*64 + (lane & 15))*A_PITCH + (((uint32_t)lane >> 4) << 4);
    const uint32_t bRow = (uint32_t)(lane & 15)*B_PITCH
                        + (uint32_t)(warpN*32 + ((lane >> 4) << 3))*2;

    uint32_t af[2][4][4], bfv[2][4];

    auto load_a = [&](int buf, uint32_t aB, int kk16){
        #pragma unroll
        for (int mf = 0; mf < 4; mf++)
            ldsm_x4(af[buf][mf], aB + aRow + (uint32_t)(mf*16)*A_PITCH + (uint32_t)kk16*32);
    };
    auto load_b = [&](uint32_t bB, int kk16){
        #pragma unroll
        for (int nq = 0; nq < 2; nq++)
            ldsm_x4t(bfv[nq], bB + (uint32_t)(kk16*16)*B_PITCH + bRow + (uint32_t)(nq*16)*2);
    };

    float acc[4][4][4];
    #pragma unroll
    for (int a = 0; a < 4; a++)
        #pragma unroll
        for (int b = 0; b < 4; b++)
            #pragma unroll
            for (int c = 0; c < 4; c++) acc[a][b][c] = 0.f;

    issue(0, 0);
    issue(1, 1);
    CP_WAIT(1);
    __syncthreads();
    load_a(0, sb + A_OFF(0), 0);

    for (int kt = 0; kt < NKT; kt++){
        const int s  = kt % 3;
        const int sn = (kt + 1) % 3;
        const uint32_t aB = sb + A_OFF(s);
        const uint32_t bB = sb + B_OFF(s);

        #pragma unroll
        for (int kk = 0; kk < 4; kk++){
            const int cur = kk & 1, nxt = cur ^ 1;
            if (kk == 0 && kt + 2 < NKT)
                issue((kt + 2) % 3, kt + 2);
            load_b(bB, kk);
            if (kk < 3){
                load_a(nxt, aB, kk + 1);
            } else if (kt + 1 < NKT){
                CP_WAIT(1);
                __syncthreads();
                load_a(nxt, sb + A_OFF(sn), 0);
            }
            #pragma unroll
            for (int mf = 0; mf < 4; mf++)
                #pragma unroll
                for (int nq = 0; nq < 2; nq++){
                    mma16816(acc[mf][2*nq],   af[cur][mf], &bfv[nq][0]);
                    mma16816(acc[mf][2*nq+1], af[cur][mf], &bfv[nq][2]);
                }
        }
    }

    const int g  = lane >> 2;
    const int tg = lane & 3;
    #pragma unroll
    for (int mf = 0; mf < 4; mf++){
        const int r0 = mBase + warpM*64 + mf*16 + g;
        const int r1 = r0 + 8;
        if (FIRST){
            #pragma unroll
            for (int nf = 0; nf < 4; nf++){
                const int c0 = nBase + warpN*32 + nf*8 + tg*2;
                *reinterpret_cast<__half2*>(&g_P0[(size_t)r0*NN + c0]) = __floats2half2_rn(acc[mf][nf][0], acc[mf][nf][1]);
                *reinterpret_cast<__half2*>(&g_P0[(size_t)r1*NN + c0]) = __floats2half2_rn(acc[mf][nf][2], acc[mf][nf][3]);
            }
        } else {
            float e0 = 0.f, e1 = 0.f;
            #pragma unroll
            for (int nf = 0; nf < 4; nf++){
                const int lc = warpN*32 + nf*8 + tg*2;
                const int c0 = nBase + lc;
                const float2 p0 = __half22float2(*reinterpret_cast<const __half2*>(&g_P0[(size_t)(r0 >> 3)*NN + c0]));
                const float2 p1 = __half22float2(*reinterpret_cast<const __half2*>(&g_P0[(size_t)(r1 >> 3)*NN + c0]));
                const float v00 = lrelu(acc[mf][nf][0] + p0.x);
                const float v01 = lrelu(acc[mf][nf][1] + p0.y);
                const float v10 = lrelu(acc[mf][nf][2] + p1.x);
                const float v11 = lrelu(acc[mf][nf][3] + p1.y);
                e0 += v00*sAw[lc] + v01*sAw[lc+1];
                e1 += v10*sAw[lc] + v11*sAw[lc+1];
                *reinterpret_cast<__half2*>(&g_Wh[(size_t)r0*NN + c0]) = __floats2half2_rn(v00, v01);
                *reinterpret_cast<__half2*>(&g_Wh[(size_t)r1*NN + c0]) = __floats2half2_rn(v10, v11);
            }
            e0 += __shfl_xor_sync(0xffffffffu, e0, 1);
            e0 += __shfl_xor_sync(0xffffffffu, e0, 2);
            e1 += __shfl_xor_sync(0xffffffffu, e1, 1);
            e1 += __shfl_xor_sync(0xffffffffu, e1, 2);
            if (tg == 0){
                atomicAdd(&g_e[(r0 >> 3)*64 + h*8 + (r0 & 7)], e0);
                atomicAdd(&g_e[(r1 >> 3)*64 + h*8 + (r1 & 7)], e1);
            }
        }
    }
}

// ---------------------------------------------------------------------------
// Merged: blocks [0,GEMM1_BLKS) -> GEMM1, both m-tiles of nTile=bx (B reuse);
//         blocks [GEMM1_BLKS,..) -> convert W[:,F:2F,:] fp32 -> g_Wf fp16
// ---------------------------------------------------------------------------
__global__ void __launch_bounds__(256, 2)
gemm1_conv(const float* __restrict__ W)
{
    if (blockIdx.x >= GEMM1_BLKS){
        const size_t qF = (size_t)F_ * F_ / 4;
        const size_t total = (size_t)H_ * qF;
        const float4* W4 = (const float4*)W;
        uint2* D = (uint2*)g_Wf;
        for (size_t i = (size_t)(blockIdx.x - GEMM1_BLKS) * 256 + threadIdx.x;
             i < total; i += (size_t)CONV_BLKS * 256){
            const size_t h = i / qF, rem = i - h * qF;
            const size_t idx = h * 2 * qF + qF + rem;   // [F:2F) slice
            D[idx] = f4_to_h4(W4[idx]);
        }
        return;
    }
    extern __shared__ char smem[];
    const int nTile = blockIdx.x;
    gemm_body<true>(smem, 0, nTile, nullptr);
    __syncthreads();                      // smem handoff between the two tiles
    gemm_body<true>(smem, 128, nTile, nullptr);
}

__global__ void __launch_bounds__(256, 2)
gat_gemm2(const float* __restrict__ att_w)
{
    extern __shared__ char smem[];
    gemm_body<false>(smem, blockIdx.x * 128, blockIdx.y, att_w);
}

// ---------------------------------------------------------------------------
// prep: [0,8) mbias; [8,16) zero ALL g_e (16384); [16,144) inputs->fp16;
//       [144, 144+PREPW_BLKS) W[:,0:F,:] fp32 -> g_Wf fp16
__global__ void __launch_bounds__(256) prep(const float* __restrict__ bias,
                                            const float* __restrict__ in,
                                            const float* __restrict__ W){
    const int tid = threadIdx.x;
    const int bx = blockIdx.x;
    if (bx < 8){
        const int f = bx * 256 + tid;
        float s = 0.f;
        #pragma unroll
        for (int h = 0; h < H_; h++) s += bias[(size_t)h*F_ + f];
        g_mbias[f] = s * 0.125f;
    } else if (bx < 16){
        const int base = (bx - 8) * 2048;          // 8 x 2048 = 16384 = B_*H_*S_
        #pragma unroll
        for (int j = 0; j < 8; j++)
            g_e[base + j*256 + tid] = 0.f;
    } else if (bx < 144){
        const float4* in4 = (const float4*)in;
        uint2* D = (uint2*)g_A2;
        const size_t total = (size_t)M2 * KK / 4;           // 1,048,576 float4
        for (size_t i = (size_t)(bx - 16) * 256 + tid; i < total; i += (size_t)128 * 256)
            D[i] = f4_to_h4(in4[i]);
    } else {
        const size_t qF = (size_t)F_ * F_ / 4;
        const size_t total = (size_t)H_ * qF;
        const float4* W4 = (const float4*)W;
        uint2* D = (uint2*)g_Wf;
        for (size_t i = (size_t)(bx - 144) * 256 + tid;
             i < total; i += (size_t)PREPW_BLKS * 256){
            const size_t h = i / qF, rem = i - h * qF;
            const size_t idx = h * 2 * qF + rem;            // [0:F) slice
            D[idx] = f4_to_h4(W4[idx]);
        }
    }
}

// out[b,s,f] = inputs + mbias + sum_h attn/H * Wh
__global__ void __launch_bounds__(256) gat_out(const float* __restrict__ in,
                                               float* __restrict__ out){
    const int bs = blockIdx.x;
    const int b = bs >> 3, s = bs & 7;
    __shared__ float sAttn[H_];
    const int tid = threadIdx.x;
    if (tid < H_){
        float ev[S_]; float mx = -1e30f;
        #pragma unroll
        for (int s2 = 0; s2 < S_; s2++){ ev[s2] = g_e[b*64 + tid*8 + s2]; mx = fmaxf(mx, ev[s2]); }
        float sum = 0.f;
        #pragma unroll
        for (int s2 = 0; s2 < S_; s2++) sum += __expf(ev[s2] - mx);
        sAttn[tid] = __expf(ev[s] - mx) * 0.125f / sum;
    }
    __syncthreads();
    const float4*  in4 = (const float4*)(in + (size_t)bs * F_);
    const float4*  mb4 = (const float4*)g_mbias;
    const __half2* w2  = (const __half2*)(g_Wh + (size_t)bs * NN);
    float4* o4 = (float4*)(out + (size_t)bs * F_);
    #pragma unroll
    for (int i = tid; i < F_/4; i += 256){
        float4 a = in4[i];
        const float4 mb = mb4[i];
        a.x += mb.x; a.y += mb.y; a.z += mb.z; a.w += mb.w;
        #pragma unroll
        for (int hh = 0; hh < H_; hh++){
            const float aw = sAttn[hh];
            const float2 lo = __half22float2(w2[hh*(F_/2) + 2*i]);
            const float2 hi = __half22float2(w2[hh*(F_/2) + 2*i + 1]);
            a.x += aw*lo.x; a.y += aw*lo.y; a.z += aw*hi.x; a.w += aw*hi.y;
        }
        o4[i] = a;
    }
}

// ---------------------------------------------------------------------------
extern "C" void kernel_launch(void* const* d_in, const int* in_sizes, int n_in,
                              void* d_out, int out_size)
{
    const float* inputs = (const float*)d_in[0];
    const float* W      = (const float*)d_in[1];
    const float* att_w  = (const float*)d_in[2];
    const float* bias   = (const float*)d_in[3];
    float* out = (float*)d_out;

    cudaFuncSetAttribute(gemm1_conv, cudaFuncAttributeMaxDynamicSharedMemorySize, SMEM_TOTAL);
    cudaFuncSetAttribute(gat_gemm2,  cudaFuncAttributeMaxDynamicSharedMemorySize, SMEM_TOTAL);

    prep<<<144 + PREPW_BLKS, 256>>>(bias, inputs, W);
    gemm1_conv<<<GEMM1_BLKS + CONV_BLKS, 256, SMEM_TOTAL>>>(W);   // GEMM1 || conv part2
    gat_gemm2<<<dim3(16, 128), 256, SMEM_TOTAL>>>(att_w);
    gat_out<<<M2, 256>>>(inputs, out);
}

// round 17
// speedup vs baseline: 1.1018x; 1.0228x over previous
#include <cuda_runtime.h>
#include <cuda_fp16.h>
#include <cstdint>

// ---------------- problem dims ----------------
#define B_  256
#define S_  8
#define F_  2048
#define H_  8
#define NN  (H_*F_)     // 16384
#define M2  (B_*S_)     // 2048
#define KK  2048        // K per split GEMM
#define ALPHA_ 0.3f

// ---------------- GEMM tiling (R7/R9 proven config) ----------------
#define NKT 32                      // 2048/64
#define A_PITCH 144
#define B_PITCH 272
#define A_ST (128*A_PITCH)          // 18432
#define B_ST (64*B_PITCH)           // 17408
#define STAGE_ST (A_ST + B_ST)      // 35840
#define A_OFF(s) ((s)*STAGE_ST)
#define B_OFF(s) ((s)*STAGE_ST + A_ST)
#define AW_OFF   (3*STAGE_ST)       // 107520
#define SMEM_TOTAL (AW_OFF + 128*4) // 108032 (2 CTAs/SM)

#define GEMM1_BLKS 128              // each does BOTH m-tiles of one nTile
#define CONV_BLKS  168              // fills remaining wave-1 slots (296 total)
#define PREPW_BLKS 896              // W part1 conversion blocks inside prep

// ---------------- device scratch ----------------
__device__ __half g_A2[(size_t)M2 * KK];          // 8MB
__device__ __half g_Wf[(size_t)H_ * 2 * F_ * F_]; // 134MB
__device__ __half g_Wh[(size_t)M2 * NN];          // 64MB
__device__ __half g_P0[(size_t)B_ * NN];          // 8MB
__device__ float  g_e [B_ * H_ * S_];             // 16384 floats
__device__ float  g_mbias[F_];

// ---------------- helpers ----------------
__device__ __forceinline__ uint32_t smem_u32(const void* p){
    uint32_t a;
    asm("{ .reg .u64 t; cvta.to.shared.u64 t, %1; cvt.u32.u64 %0, t; }" : "=r"(a) : "l"(p));
    return a;
}
__device__ __forceinline__ void ldsm_x4(uint32_t* r, uint32_t addr){
    asm volatile("ldmatrix.sync.aligned.m8n8.x4.shared.b16 {%0,%1,%2,%3}, [%4];"
                 : "=r"(r[0]),"=r"(r[1]),"=r"(r[2]),"=r"(r[3]) : "r"(addr));
}
__device__ __forceinline__ void ldsm_x4t(uint32_t* r, uint32_t addr){
    asm volatile("ldmatrix.sync.aligned.m8n8.x4.trans.shared.b16 {%0,%1,%2,%3}, [%4];"
                 : "=r"(r[0]),"=r"(r[1]),"=r"(r[2]),"=r"(r[3]) : "r"(addr));
}
__device__ __forceinline__ void mma16816(float* c, const uint32_t* a, const uint32_t* b){
    asm volatile("mma.sync.aligned.m16n8k16.row.col.f32.f16.f16.f32 "
                 "{%0,%1,%2,%3}, {%4,%5,%6,%7}, {%8,%9}, {%0,%1,%2,%3};"
                 : "+f"(c[0]),"+f"(c[1]),"+f"(c[2]),"+f"(c[3])
                 : "r"(a[0]),"r"(a[1]),"r"(a[2]),"r"(a[3]),"r"(b[0]),"r"(b[1]));
}
__device__ __forceinline__ void cp16(uint32_t dst, const void* src){
    asm volatile("cp.async.cg.shared.global [%0], [%1], 16;" :: "r"(dst), "l"(src) : "memory");
}
#define CP_COMMIT() asm volatile("cp.async.commit_group;" ::: "memory")
#define CP_WAIT(n)  asm volatile("cp.async.wait_group %0;" :: "n"(n) : "memory")
__device__ __forceinline__ float lrelu(float z){ return z > 0.f ? z : ALPHA_ * z; }

__device__ __forceinline__ uint2 f4_to_h4(float4 v){
    __half2 lo = __floats2half2_rn(v.x, v.y);
    __half2 hi = __floats2half2_rn(v.z, v.w);
    uint2 pk;
    pk.x = *reinterpret_cast<uint32_t*>(&lo);
    pk.y = *reinterpret_cast<uint32_t*>(&hi);
    return pk;
}

// ---------------------------------------------------------------------------
// Shared GEMM body (R7/R9 proven): 256 thr, warp grid 2Mx4N, warp tile 64x32,
// BK=64, 3 stages, A-frag double-buffered.
// FIRST:  P0[b,n](fp16) = inputs[b,0,:](fp16) @ Wf[h,0:F,:]
// !FIRST: Wh = lrelu(A2 @ Wf[h,F:2F,:] + P0);  e += Wh . att_w
// ---------------------------------------------------------------------------
template<bool FIRST>
__device__ __forceinline__ void gemm_body(char* smem, int mBase, int nTile,
                                          const float* __restrict__ att_w)
{
    const uint32_t sb = smem_u32(smem);
    const int tid   = threadIdx.x;
    const int lane  = tid & 31;
    const int wid   = tid >> 5;
    const int warpM = wid & 1;
    const int warpN = wid >> 1;

    const int nBase = nTile * 128;
    const int h     = nTile >> 4;
    const int f0    = (nTile & 15) * 128;

    const size_t aStride = FIRST ? (size_t)(8*KK) : (size_t)KK;
    const __half* gB = g_Wf + ((size_t)h*(2*F_) + (FIRST ? 0 : F_)) * F_ + f0;

    float* sAw = (float*)(smem + AW_OFF);
    if (!FIRST && tid < 128) sAw[tid] = att_w[(size_t)h*F_ + f0 + tid];

    const __half* aSrc = g_A2 + (size_t)(mBase + (tid >> 3))*aStride + (tid & 7)*8;
    const __half* bSrc = gB   + (size_t)(tid >> 4)*F_ + (tid & 15)*8;
    const uint32_t aDst = sb + (uint32_t)(tid >> 3)*A_PITCH + (uint32_t)(tid & 7)*16;
    const uint32_t bDst = sb + A_ST + (uint32_t)(tid >> 4)*B_PITCH + (uint32_t)(tid & 15)*16;

    auto issue = [&](int s, int kt){
        const __half* a = aSrc + (size_t)kt * 64;
        const __half* b = bSrc + (size_t)kt * 64 * F_;
        const uint32_t ad = aDst + (uint32_t)s*STAGE_ST;
        const uint32_t bd = bDst + (uint32_t)s*STAGE_ST;
        #pragma unroll
        for (int i = 0; i < 4; i++)
            cp16(ad + (uint32_t)(i*32*A_PITCH), a + (size_t)(i*32)*aStride);
        #pragma unroll
        for (int i = 0; i < 4; i++)
            cp16(bd + (uint32_t)(i*16*B_PITCH), b + (size_t)(i*16)*F_);
        CP_COMMIT();
    };

    const uint32_t aRow = (uint32_t)(warpM*64 + (lane & 15))*A_PITCH + (((uint32_t)lane >> 4) << 4);
    const uint32_t bRow = (uint32_t)(lane & 15)*B_PITCH
                        + (uint32_t)(warpN*32 + ((lane >> 4) << 3))*2;

    uint32_t af[2][4][4], bfv[2][4];

    auto load_a = [&](int buf, uint32_t aB, int kk16){
        #pragma unroll
        for (int mf = 0; mf < 4; mf++)
            ldsm_x4(af[buf][mf], aB + aRow + (uint32_t)(mf*16)*A_PITCH + (uint32_t)kk16*32);
    };
    auto load_b = [&](uint32_t bB, int kk16){
        #pragma unroll
        for (int nq = 0; nq < 2; nq++)
            ldsm_x4t(bfv[nq], bB + (uint32_t)(kk16*16)*B_PITCH + bRow + (uint32_t)(nq*16)*2);
    };

    float acc[4][4][4];
    #pragma unroll
    for (int a = 0; a < 4; a++)
        #pragma unroll
        for (int b = 0; b < 4; b++)
            #pragma unroll
            for (int c = 0; c < 4; c++) acc[a][b][c] = 0.f;

    issue(0, 0);
    issue(1, 1);
    CP_WAIT(1);
    __syncthreads();
    load_a(0, sb + A_OFF(0), 0);

    for (int kt = 0; kt < NKT; kt++){
        const int s  = kt % 3;
        const int sn = (kt + 1) % 3;
        const uint32_t aB = sb + A_OFF(s);
        const uint32_t bB = sb + B_OFF(s);
        const bool issued = (kt + 2 < NKT);

        #pragma unroll
        for (int kk = 0; kk < 4; kk++){
            const int cur = kk & 1, nxt = cur ^ 1;
            if (kk == 0 && issued)
                issue((kt + 2) % 3, kt + 2);
            load_b(bB, kk);
            if (kk < 3){
                load_a(nxt, aB, kk + 1);
            } else if (kt + 1 < NKT){
                // Race fix: if no new group was issued this kt, the next-stage
                // group may be the ONLY one outstanding -> must drain fully.
                if (issued) { CP_WAIT(1); } else { CP_WAIT(0); }
                __syncthreads();
                load_a(nxt, sb + A_OFF(sn), 0);
            }
            #pragma unroll
            for (int mf = 0; mf < 4; mf++)
                #pragma unroll
                for (int nq = 0; nq < 2; nq++){
                    mma16816(acc[mf][2*nq],   af[cur][mf], &bfv[nq][0]);
                    mma16816(acc[mf][2*nq+1], af[cur][mf], &bfv[nq][2]);
                }
        }
    }

    const int g  = lane >> 2;
    const int tg = lane & 3;
    #pragma unroll
    for (int mf = 0; mf < 4; mf++){
        const int r0 = mBase + warpM*64 + mf*16 + g;
        const int r1 = r0 + 8;
        if (FIRST){
            #pragma unroll
            for (int nf = 0; nf < 4; nf++){
                const int c0 = nBase + warpN*32 + nf*8 + tg*2;
                *reinterpret_cast<__half2*>(&g_P0[(size_t)r0*NN + c0]) = __floats2half2_rn(acc[mf][nf][0], acc[mf][nf][1]);
                *reinterpret_cast<__half2*>(&g_P0[(size_t)r1*NN + c0]) = __floats2half2_rn(acc[mf][nf][2], acc[mf][nf][3]);
            }
        } else {
            float e0 = 0.f, e1 = 0.f;
            #pragma unroll
            for (int nf = 0; nf < 4; nf++){
                const int lc = warpN*32 + nf*8 + tg*2;
                const int c0 = nBase + lc;
                const float2 p0 = __half22float2(*reinterpret_cast<const __half2*>(&g_P0[(size_t)(r0 >> 3)*NN + c0]));
                const float2 p1 = __half22float2(*reinterpret_cast<const __half2*>(&g_P0[(size_t)(r1 >> 3)*NN + c0]));
                const float v00 = lrelu(acc[mf][nf][0] + p0.x);
                const float v01 = lrelu(acc[mf][nf][1] + p0.y);
                const float v10 = lrelu(acc[mf][nf][2] + p1.x);
                const float v11 = lrelu(acc[mf][nf][3] + p1.y);
                e0 += v00*sAw[lc] + v01*sAw[lc+1];
                e1 += v10*sAw[lc] + v11*sAw[lc+1];
                *reinterpret_cast<__half2*>(&g_Wh[(size_t)r0*NN + c0]) = __floats2half2_rn(v00, v01);
                *reinterpret_cast<__half2*>(&g_Wh[(size_t)r1*NN + c0]) = __floats2half2_rn(v10, v11);
            }
            e0 += __shfl_xor_sync(0xffffffffu, e0, 1);
            e0 += __shfl_xor_sync(0xffffffffu, e0, 2);
            e1 += __shfl_xor_sync(0xffffffffu, e1, 1);
            e1 += __shfl_xor_sync(0xffffffffu, e1, 2);
            if (tg == 0){
                atomicAdd(&g_e[(r0 >> 3)*64 + h*8 + (r0 & 7)], e0);
                atomicAdd(&g_e[(r1 >> 3)*64 + h*8 + (r1 & 7)], e1);
            }
        }
    }
}

// ---------------------------------------------------------------------------
// Merged: blocks [0,GEMM1_BLKS) -> GEMM1, both m-tiles of nTile=bx (B reuse);
//         blocks [GEMM1_BLKS,..) -> convert W[:,F:2F,:] fp32 -> g_Wf fp16
// ---------------------------------------------------------------------------
__global__ void __launch_bounds__(256, 2)
gemm1_conv(const float* __restrict__ W)
{
    if (blockIdx.x >= GEMM1_BLKS){
        const size_t qF = (size_t)F_ * F_ / 4;
        const size_t total = (size_t)H_ * qF;
        const float4* W4 = (const float4*)W;
        uint2* D = (uint2*)g_Wf;
        for (size_t i = (size_t)(blockIdx.x - GEMM1_BLKS) * 256 + threadIdx.x;
             i < total; i += (size_t)CONV_BLKS * 256){
            const size_t h = i / qF, rem = i - h * qF;
            const size_t idx = h * 2 * qF + qF + rem;   // [F:2F) slice
            D[idx] = f4_to_h4(W4[idx]);
        }
        return;
    }
    extern __shared__ char smem[];
    const int nTile = blockIdx.x;
    gemm_body<true>(smem, 0, nTile, nullptr);
    __syncthreads();                      // smem handoff between the two tiles
    gemm_body<true>(smem, 128, nTile, nullptr);
}

__global__ void __launch_bounds__(256, 2)
gat_gemm2(const float* __restrict__ att_w)
{
    extern __shared__ char smem[];
    gemm_body<false>(smem, blockIdx.x * 128, blockIdx.y, att_w);
}

// ---------------------------------------------------------------------------
// prep: [0,8) mbias; [8,16) zero ALL g_e (16384); [16,144) inputs->fp16;
//       [144, 144+PREPW_BLKS) W[:,0:F,:] fp32 -> g_Wf fp16
__global__ void __launch_bounds__(256) prep(const float* __restrict__ bias,
                                            const float* __restrict__ in,
                                            const float* __restrict__ W){
    const int tid = threadIdx.x;
    const int bx = blockIdx.x;
    if (bx < 8){
        const int f = bx * 256 + tid;
        float s = 0.f;
        #pragma unroll
        for (int h = 0; h < H_; h++) s += bias[(size_t)h*F_ + f];
        g_mbias[f] = s * 0.125f;
    } else if (bx < 16){
        const int base = (bx - 8) * 2048;          // 8 x 2048 = 16384 = B_*H_*S_
        #pragma unroll
        for (int j = 0; j < 8; j++)
            g_e[base + j*256 + tid] = 0.f;
    } else if (bx < 144){
        const float4* in4 = (const float4*)in;
        uint2* D = (uint2*)g_A2;
        const size_t total = (size_t)M2 * KK / 4;           // 1,048,576 float4
        for (size_t i = (size_t)(bx - 16) * 256 + tid; i < total; i += (size_t)128 * 256)
            D[i] = f4_to_h4(in4[i]);
    } else {
        const size_t qF = (size_t)F_ * F_ / 4;
        const size_t total = (size_t)H_ * qF;
        const float4* W4 = (const float4*)W;
        uint2* D = (uint2*)g_Wf;
        for (size_t i = (size_t)(bx - 144) * 256 + tid;
             i < total; i += (size_t)PREPW_BLKS * 256){
            const size_t h = i / qF, rem = i - h * qF;
            const size_t idx = h * 2 * qF + rem;            // [0:F) slice
            D[idx] = f4_to_h4(W4[idx]);
        }
    }
}

// out[b,s,f] = inputs + mbias + sum_h attn/H * Wh
// Vectorized: each thread owns one 8-wide f-chunk; Wh read as uint4 (LDG.128).
__global__ void __launch_bounds__(256) gat_out(const float* __restrict__ in,
                                               float* __restrict__ out){
    const int bs = blockIdx.x;
    const int b = bs >> 3, s = bs & 7;
    __shared__ float sAttn[H_];
    const int tid = threadIdx.x;
    if (tid < H_){
        float ev[S_]; float mx = -1e30f;
        #pragma unroll
        for (int s2 = 0; s2 < S_; s2++){ ev[s2] = g_e[b*64 + tid*8 + s2]; mx = fmaxf(mx, ev[s2]); }
        float sum = 0.f;
        #pragma unroll
        for (int s2 = 0; s2 < S_; s2++) sum += __expf(ev[s2] - mx);
        sAttn[tid] = __expf(ev[s] - mx) * 0.125f / sum;
    }
    __syncthreads();

    const float4* in4 = (const float4*)(in + (size_t)bs * F_);
    const float4* mb4 = (const float4*)g_mbias;
    const uint4*  w4  = (const uint4*)(g_Wh + (size_t)bs * NN);   // [h*256 + chunk]
    float4* o4 = (float4*)(out + (size_t)bs * F_);

    const int i = tid;                 // f-chunk index (8 halves), 256 chunks total
    float4 a0 = in4[2*i];
    float4 a1 = in4[2*i + 1];
    const float4 m0 = mb4[2*i];
    const float4 m1 = mb4[2*i + 1];
    a0.x += m0.x; a0.y += m0.y; a0.z += m0.z; a0.w += m0.w;
    a1.x += m1.x; a1.y += m1.y; a1.z += m1.z; a1.w += m1.w;

    #pragma unroll
    for (int hh = 0; hh < H_; hh++){
        const uint4 w = w4[hh*256 + i];
        const float aw = sAttn[hh];
        const float2 p0 = __half22float2(*reinterpret_cast<const __half2*>(&w.x));
        const float2 p1 = __half22float2(*reinterpret_cast<const __half2*>(&w.y));
        const float2 p2 = __half22float2(*reinterpret_cast<const __half2*>(&w.z));
        const float2 p3 = __half22float2(*reinterpret_cast<const __half2*>(&w.w));
        a0.x += aw*p0.x; a0.y += aw*p0.y; a0.z += aw*p1.x; a0.w += aw*p1.y;
        a1.x += aw*p2.x; a1.y += aw*p2.y; a1.z += aw*p3.x; a1.w += aw*p3.y;
    }
    o4[2*i]     = a0;
    o4[2*i + 1] = a1;
}

// ---------------------------------------------------------------------------
extern "C" void kernel_launch(void* const* d_in, const int* in_sizes, int n_in,
                              void* d_out, int out_size)
{
    const float* inputs = (const float*)d_in[0];
    const float* W      = (const float*)d_in[1];
    const float* att_w  = (const float*)d_in[2];
    const float* bias   = (const float*)d_in[3];
    float* out = (float*)d_out;

    cudaFuncSetAttribute(gemm1_conv, cudaFuncAttributeMaxDynamicSharedMemorySize, SMEM_TOTAL);
    cudaFuncSetAttribute(gat_gemm2,  cudaFuncAttributeMaxDynamicSharedMemorySize, SMEM_TOTAL);

    prep<<<144 + PREPW_BLKS, 256>>>(bias, inputs, W);
    gemm1_conv<<<GEMM1_BLKS + CONV_BLKS, 256, SMEM_TOTAL>>>(W);   // GEMM1 || conv part2
    gat_gemm2<<<dim3(16, 128), 256, SMEM_TOTAL>>>(att_w);
    gat_out<<<M2, 256>>>(inputs, out);
}